// round 9
// baseline (speedup 1.0000x reference)
#include <cuda_runtime.h>
#include <cuda_fp16.h>
#include <math.h>

// Problem constants (fixed by the dataset)
#define NMAX   100000
#define EMAX   1000000
#define DIM    64
#define Hdim   14     // H = 2*LAT
#define PD     16     // P = (LAT+1)*R
#define LATC   7
#define OUTC   30     // 7 loc + 7 scale + 14 U + 2 m
#define SP_INV_1 0.5413248546129181f

// ---------------- scratch (static device globals; zero-init at load) -------
__device__ uint2    g_Y1h[NMAX * 4];   // X@W1 (fp16, padded 16 feats, pads=0)
__device__ uint2    g_Y2h[NMAX * 4];   // relu(agg1)@W2 (fp16)
__device__ int      g_cnt[NMAX + 1];   // degree histogram; [NMAX]=scan total. SELF-RESTORED to 0 each call.
__device__ int      g_start[NMAX];     // bucket base offsets (disjoint)
__device__ int      g_rank[EMAX];      // within-row rank of each edge
__device__ int2     g_edge[EMAX];      // (col, val_bits) bucketed by row
// monotone phase counters (never reset): 0=hist 1=scan 2=gemm+fill 3=agg1 4=agg2
__device__ unsigned g_ctr[5];
__device__ unsigned g_done_calls;      // completed-call counter (monotone)

// ---------------- phase barrier helpers -------------------------------------
__device__ __forceinline__ void phase_wait(int idx, unsigned target) {
    if (threadIdx.x == 0) {
        while (*((volatile unsigned*)&g_ctr[idx]) < target)
            __nanosleep(64);
        __threadfence();   // acquire; gpu-scope fence flushes L1D on sm_103a
    }
    __syncthreads();
}
__device__ __forceinline__ void phase_arrive(int idx) {
    __syncthreads();
    if (threadIdx.x == 0) {
        __threadfence();   // release
        atomicAdd(&g_ctr[idx], 1u);
    }
}

// ---------------- math helpers ----------------------------------------------
__device__ __forceinline__ uint2 pack4h(float a, float b, float c, float d) {
    half2 lo = __floats2half2_rn(a, b);
    half2 hi = __floats2half2_rn(c, d);
    uint2 r;
    r.x = *reinterpret_cast<unsigned*>(&lo);
    r.y = *reinterpret_cast<unsigned*>(&hi);
    return r;
}
__device__ __forceinline__ void fma_h4(float4& acc, uint2 r, float v) {
    half2 lo = *reinterpret_cast<half2*>(&r.x);
    half2 hi = *reinterpret_cast<half2*>(&r.y);
    float2 f01 = __half22float2(lo);
    float2 f23 = __half22float2(hi);
    acc.x += v * f01.x; acc.y += v * f01.y;
    acc.z += v * f23.x; acc.w += v * f23.y;
}
__device__ __forceinline__ float ftanh(float x) {
    x = fminf(fmaxf(x, -15.f), 15.f);
    float e = __expf(2.f * x);
    return (e - 1.f) / (e + 1.f);
}
__device__ __forceinline__ float fsoftplus(float x) {
    return log1pf(__expf(x));   // input range ~[-0.46, 1.54]: safe
}

// 4 lanes per node; lane owns chunk q. Edge loop unrolled x8/x4/x1 for MLP.
__device__ __forceinline__ float4 csr_agg4(const uint2* __restrict__ src,
                                           int s, int cnt, int q) {
    int e = s, end = s + cnt;
    float4 acc = make_float4(0.f, 0.f, 0.f, 0.f);

    for (; e + 8 <= end; e += 8) {
        int2 ed[8];
#pragma unroll
        for (int u = 0; u < 8; ++u) ed[u] = __ldg(&g_edge[e + u]);
        uint2 sv[8];
#pragma unroll
        for (int u = 0; u < 8; ++u) sv[u] = __ldg(&src[(long)ed[u].x * 4 + q]);
#pragma unroll
        for (int u = 0; u < 8; ++u)
            fma_h4(acc, sv[u], __int_as_float(ed[u].y));
    }
    if (e + 4 <= end) {
        int2 ed[4];
#pragma unroll
        for (int u = 0; u < 4; ++u) ed[u] = __ldg(&g_edge[e + u]);
        uint2 sv[4];
#pragma unroll
        for (int u = 0; u < 4; ++u) sv[u] = __ldg(&src[(long)ed[u].x * 4 + q]);
#pragma unroll
        for (int u = 0; u < 4; ++u)
            fma_h4(acc, sv[u], __int_as_float(ed[u].y));
        e += 4;
    }
    for (; e < end; ++e) {
        int2 ed = __ldg(&g_edge[e]);
        uint2 sv = __ldg(&src[(long)ed.x * 4 + q]);
        fma_h4(acc, sv, __int_as_float(ed.y));
    }
    return acc;
}

__device__ __forceinline__ void group_bcast(float4 acc, float* h, int lane) {
    int base = lane & ~3;
#pragma unroll
    for (int sq = 0; sq < 4; ++sq) {
        h[4 * sq + 0] = __shfl_sync(0xffffffffu, acc.x, base + sq);
        h[4 * sq + 1] = __shfl_sync(0xffffffffu, acc.y, base + sq);
        h[4 * sq + 2] = __shfl_sync(0xffffffffu, acc.z, base + sq);
        h[4 * sq + 3] = __shfl_sync(0xffffffffu, acc.w, base + sq);
    }
}

// ---------------- THE mega kernel: all phases, one launch -------------------
__global__ void k_mega(const float* __restrict__ X,
                       const int* __restrict__ rows,
                       const int* __restrict__ cols,
                       const float* __restrict__ vals,
                       const float* __restrict__ W1,
                       const float* __restrict__ W2,
                       const float* __restrict__ Wd1,
                       const float* __restrict__ bd1,
                       const float* __restrict__ Wd2,
                       const float* __restrict__ bd2,
                       float* __restrict__ out,
                       int N, int E, int gN, int gE, int g4N) {
    __shared__ float sbuf[920];            // unioned shared scratch
    unsigned cprev = *((volatile unsigned*)&g_done_calls);
    unsigned call  = cprev + 1;
    int tid = threadIdx.x;
    int b = blockIdx.x;

    // ===================== P0: gemm1  Y1h = pack(X @ W1) ====================
    if (b < gN) {
        float* sW = sbuf;                  // 896 floats
        for (int t = tid; t < DIM * Hdim; t += blockDim.x)
            sW[t] = W1[t];
        __syncthreads();

        int i = b * blockDim.x + tid;
        if (i < N) {
            const float4* x4 = (const float4*)(X + (long)i * DIM);
            float acc[Hdim];
#pragma unroll
            for (int j = 0; j < Hdim; ++j) acc[j] = 0.f;
#pragma unroll
            for (int k4 = 0; k4 < DIM / 4; ++k4) {
                float4 x = x4[k4];
                const float* w = &sW[k4 * 4 * Hdim];
#pragma unroll
                for (int j = 0; j < Hdim; ++j)
                    acc[j] += x.x * w[j] + x.y * w[Hdim + j]
                            + x.z * w[2 * Hdim + j] + x.w * w[3 * Hdim + j];
            }
            g_Y1h[i * 4 + 0] = pack4h(acc[0], acc[1], acc[2], acc[3]);
            g_Y1h[i * 4 + 1] = pack4h(acc[4], acc[5], acc[6], acc[7]);
            g_Y1h[i * 4 + 2] = pack4h(acc[8], acc[9], acc[10], acc[11]);
            g_Y1h[i * 4 + 3] = pack4h(acc[12], acc[13], 0.f, 0.f);
        }
        phase_arrive(2);                   // shares counter with fill
        return;
    }
    b -= gN;

    // ===================== P1: histogram + rank =============================
    if (b < gE) {
        int e = b * blockDim.x + tid;
        if (e < E) {
            int rk = atomicAdd(&g_cnt[rows[e]], 1);
            g_rank[e] = rk;
        }
        phase_arrive(0);
        return;
    }
    b -= gE;

    // ===================== P2: scan (bucket bases) ==========================
    if (b < gN) {
        phase_wait(0, call * (unsigned)gE);

        int i = b * blockDim.x + tid;
        int v = (i < N) ? __ldg(&g_cnt[i]) : 0;

        int lane = tid & 31, w = tid >> 5;
        int x = v;
#pragma unroll
        for (int off = 1; off < 32; off <<= 1) {
            int y = __shfl_up_sync(0xffffffffu, x, off);
            if (lane >= off) x += y;
        }
        int* wsum = (int*)&sbuf[900];
        int* bbase = (int*)&sbuf[910];
        if (lane == 31) wsum[w] = x;
        __syncthreads();
        if (tid < 8) {
            int s = wsum[tid];
#pragma unroll
            for (int off = 1; off < 8; off <<= 1) {
                int y = __shfl_up_sync(0xffu, s, off);
                if (tid >= off) s += y;
            }
            wsum[tid] = s;
            if (tid == 7) *bbase = atomicAdd(&g_cnt[NMAX], s);
        }
        __syncthreads();
        if (i < N) {
            int excl = (x - v) + ((w > 0) ? wsum[w - 1] : 0);
            g_start[i] = *bbase + excl;
        }
        phase_arrive(1);
        return;
    }
    b -= gN;

    // ===================== P3: fill (atomic-free scatter) ===================
    if (b < gE) {
        phase_wait(1, call * (unsigned)gN);
        int e = b * blockDim.x + tid;
        if (e < E) {
            int r = rows[e];
            int pos = __ldg(&g_start[r]) + __ldg(&g_rank[e]);
            g_edge[pos] = make_int2(cols[e], __float_as_int(vals[e]));
        }
        phase_arrive(2);
        return;
    }
    b -= gE;

    // ===================== P4: agg1  Y2h = pack(relu(agg(Y1h)) @ W2) ========
    if (b < g4N) {
        // wait for gemm (gN) + fill (gE) on shared counter 2
        phase_wait(2, call * (unsigned)(gN + gE));

        float* sW = sbuf;                  // W2 padded 14x16
        for (int t = tid; t < Hdim * 16; t += blockDim.x) {
            int k = t >> 4, j = t & 15;
            sW[t] = (j < Hdim) ? W2[k * Hdim + j] : 0.f;
        }
        __syncthreads();

        int gt = b * blockDim.x + tid;
        int i = gt >> 2, q = gt & 3;
        bool valid = (i < N);

        float4 acc = make_float4(0.f, 0.f, 0.f, 0.f);
        if (valid) {
            int s = __ldg(&g_start[i]);
            int c = __ldg(&g_cnt[i]);
            acc = csr_agg4(g_Y1h, s, c, q);
        }
        acc.x = fmaxf(acc.x, 0.f); acc.y = fmaxf(acc.y, 0.f);
        acc.z = fmaxf(acc.z, 0.f); acc.w = fmaxf(acc.w, 0.f);

        float h[16];
        group_bcast(acc, h, tid & 31);

        int j0 = q * 4;
        float y[4] = {0.f, 0.f, 0.f, 0.f};
#pragma unroll
        for (int k = 0; k < Hdim; ++k) {
            float hk = h[k];
#pragma unroll
            for (int d = 0; d < 4; ++d)
                y[d] += hk * sW[k * 16 + j0 + d];
        }
        if (valid)
            g_Y2h[(long)i * 4 + q] = pack4h(y[0], y[1], y[2], y[3]);

        phase_arrive(3);
        return;
    }
    b -= g4N;

    // ===================== P5: agg2 -> heads -> out (+ state restore) =======
    {
        phase_wait(3, call * (unsigned)g4N);

        float* sW1 = sbuf;                 // 224
        float* sW2 = sbuf + 224;           // 224
        float* sB1 = sbuf + 448;           // 16
        float* sB2 = sbuf + 464;           // 16
        for (int t = tid; t < Hdim * 16; t += blockDim.x) {
            int k = t >> 4, j = t & 15;
            sW1[t] = (j < Hdim) ? Wd1[k * Hdim + j] : 0.f;
            sW2[t] = Wd2[k * PD + j];
        }
        if (tid < 16) {
            sB1[tid] = (tid < Hdim) ? bd1[tid] : 0.f;
            sB2[tid] = bd2[tid];
        }
        __syncthreads();

        int gt = b * blockDim.x + tid;
        int i = gt >> 2, q = gt & 3;
        bool valid = (i < N);

        float4 acc = make_float4(0.f, 0.f, 0.f, 0.f);
        if (valid) {
            int s = __ldg(&g_start[i]);
            int c = __ldg(&g_cnt[i]);
            acc = csr_agg4(g_Y2h, s, c, q);
            if (q == 0) g_cnt[i] = 0;      // self-restore histogram for next call
        }
        acc.x = fmaxf(acc.x, 0.f); acc.y = fmaxf(acc.y, 0.f);
        acc.z = fmaxf(acc.z, 0.f); acc.w = fmaxf(acc.w, 0.f);

        float h[16];
        group_bcast(acc, h, tid & 31);

        int j0 = q * 4;
        float pd[4], pp[4];
#pragma unroll
        for (int d = 0; d < 4; ++d) { pd[d] = sB1[j0 + d]; pp[d] = sB2[j0 + d]; }
#pragma unroll
        for (int k = 0; k < Hdim; ++k) {
            float hk = h[k];
#pragma unroll
            for (int d = 0; d < 4; ++d) {
                pd[d] += hk * sW1[k * 16 + j0 + d];
                pp[d] += hk * sW2[k * 16 + j0 + d];
            }
        }

        if (valid) {
            float* o = out + (long)i * OUTC;
#pragma unroll
            for (int d = 0; d < 4; ++d) {
                int j = j0 + d;
                if (j < Hdim) {
                    float t = ftanh(pd[d]);
                    o[j] = (j < LATC) ? t : fsoftplus(t + SP_INV_1);
                }
                o[Hdim + j] = ftanh(pp[d]);   // U(14) + m(2)
            }
        }

        // finalize: last agg2 block restores scan total and bumps call counter
        __syncthreads();
        if (tid == 0) {
            __threadfence();
            unsigned fin = atomicAdd(&g_ctr[4], 1u) + 1u;
            if (fin == call * (unsigned)g4N) {
                g_cnt[NMAX] = 0;           // restore scan-total accumulator
                __threadfence();
                atomicAdd(&g_done_calls, 1u);
            }
        }
    }
}

// ---------------- launch: ONE kernel ----------------------------------------
extern "C" void kernel_launch(void* const* d_in, const int* in_sizes, int n_in,
                              void* d_out, int out_size) {
    const float* X    = (const float*)d_in[0];
    const int*   rows = (const int*)d_in[1];
    const int*   cols = (const int*)d_in[2];
    const float* vals = (const float*)d_in[3];
    const float* W1   = (const float*)d_in[4];
    const float* W2   = (const float*)d_in[5];
    const float* Wd1  = (const float*)d_in[6];
    const float* bd1  = (const float*)d_in[7];
    const float* Wd2  = (const float*)d_in[8];
    const float* bd2  = (const float*)d_in[9];
    float* out = (float*)d_out;

    int N = in_sizes[0] / DIM;
    int E = in_sizes[1];

    const int T = 256;
    int gN  = (N + T - 1) / T;
    int gE  = (E + T - 1) / T;
    int g4N = (N * 4 + T - 1) / T;

    int total = gN + gE + gN + gE + g4N + g4N;
    k_mega<<<total, T>>>(X, rows, cols, vals, W1, W2, Wd1, bd1, Wd2, bd2,
                         out, N, E, gN, gE, g4N);
}

// round 10
// speedup vs baseline: 1.1680x; 1.1680x over previous
#include <cuda_runtime.h>
#include <cuda_fp16.h>
#include <math.h>

// Problem constants (fixed by the dataset)
#define NMAX   100000
#define EMAX   1000000
#define DIM    64
#define Hdim   14     // H = 2*LAT
#define PD     16     // P = (LAT+1)*R
#define LATC   7
#define OUTC   30     // 7 loc + 7 scale + 14 U + 2 m
#define SP_INV_1 0.5413248546129181f
#define NBLK   740    // 5 blocks/SM x 148 SMs -- guaranteed co-resident

// ---------------- scratch (static device globals; zero-init at load) -------
__device__ uint2    g_Y1h[NMAX * 4];   // X@W1 (fp16, padded 16 feats, pads=0)
__device__ uint2    g_Y2h[NMAX * 4];   // relu(agg1)@W2 (fp16)
__device__ int      g_cnt[NMAX + 1];   // degree histogram; [NMAX]=scan total. Self-restored to 0 each call.
__device__ int      g_start[NMAX];     // bucket base offsets (disjoint)
__device__ int      g_rank[EMAX];      // within-row rank of each edge
__device__ int2     g_edge[EMAX];      // (col, val_bits) bucketed by row
// monotone sync state (never reset)
__device__ unsigned g_bar;             // barrier arrivals: 4*NBLK per call
__device__ unsigned g_fin;             // finish arrivals:  NBLK per call
__device__ unsigned g_calls;           // completed calls

// ---------------- global barrier (all CTAs resident => safe) ---------------
__device__ __forceinline__ void gbar(unsigned k, unsigned base) {
    __syncthreads();
    if (threadIdx.x == 0) {
        __threadfence();                     // release
        atomicAdd(&g_bar, 1u);
        unsigned target = base * 4u * NBLK + k * NBLK;
        while (*((volatile unsigned*)&g_bar) < target)
            __nanosleep(128);
        __threadfence();                     // acquire; flushes L1D (gpu scope)
    }
    __syncthreads();
}

// ---------------- math helpers ----------------------------------------------
__device__ __forceinline__ uint2 pack4h(float a, float b, float c, float d) {
    half2 lo = __floats2half2_rn(a, b);
    half2 hi = __floats2half2_rn(c, d);
    uint2 r;
    r.x = *reinterpret_cast<unsigned*>(&lo);
    r.y = *reinterpret_cast<unsigned*>(&hi);
    return r;
}
__device__ __forceinline__ void fma_h4(float4& acc, uint2 r, float v) {
    half2 lo = *reinterpret_cast<half2*>(&r.x);
    half2 hi = *reinterpret_cast<half2*>(&r.y);
    float2 f01 = __half22float2(lo);
    float2 f23 = __half22float2(hi);
    acc.x += v * f01.x; acc.y += v * f01.y;
    acc.z += v * f23.x; acc.w += v * f23.y;
}
__device__ __forceinline__ float ftanh(float x) {
    x = fminf(fmaxf(x, -15.f), 15.f);
    float e = __expf(2.f * x);
    return (e - 1.f) / (e + 1.f);
}
__device__ __forceinline__ float fsoftplus(float x) {
    return log1pf(__expf(x));   // input range ~[-0.46, 1.54]: safe
}

// 4 lanes per node; lane owns chunk q. Edge loop unrolled x8/x4/x1 for MLP.
__device__ __forceinline__ float4 csr_agg4(const uint2* __restrict__ src,
                                           int s, int cnt, int q) {
    int e = s, end = s + cnt;
    float4 acc = make_float4(0.f, 0.f, 0.f, 0.f);

    for (; e + 8 <= end; e += 8) {
        int2 ed[8];
#pragma unroll
        for (int u = 0; u < 8; ++u) ed[u] = __ldg(&g_edge[e + u]);
        uint2 sv[8];
#pragma unroll
        for (int u = 0; u < 8; ++u) sv[u] = __ldg(&src[(long)ed[u].x * 4 + q]);
#pragma unroll
        for (int u = 0; u < 8; ++u)
            fma_h4(acc, sv[u], __int_as_float(ed[u].y));
    }
    if (e + 4 <= end) {
        int2 ed[4];
#pragma unroll
        for (int u = 0; u < 4; ++u) ed[u] = __ldg(&g_edge[e + u]);
        uint2 sv[4];
#pragma unroll
        for (int u = 0; u < 4; ++u) sv[u] = __ldg(&src[(long)ed[u].x * 4 + q]);
#pragma unroll
        for (int u = 0; u < 4; ++u)
            fma_h4(acc, sv[u], __int_as_float(ed[u].y));
        e += 4;
    }
    for (; e < end; ++e) {
        int2 ed = __ldg(&g_edge[e]);
        uint2 sv = __ldg(&src[(long)ed.x * 4 + q]);
        fma_h4(acc, sv, __int_as_float(ed.y));
    }
    return acc;
}

__device__ __forceinline__ void group_bcast(float4 acc, float* h, int lane) {
    int base = lane & ~3;
#pragma unroll
    for (int sq = 0; sq < 4; ++sq) {
        h[4 * sq + 0] = __shfl_sync(0xffffffffu, acc.x, base + sq);
        h[4 * sq + 1] = __shfl_sync(0xffffffffu, acc.y, base + sq);
        h[4 * sq + 2] = __shfl_sync(0xffffffffu, acc.z, base + sq);
        h[4 * sq + 3] = __shfl_sync(0xffffffffu, acc.w, base + sq);
    }
}

// ---------------- persistent kernel: all phases, co-resident grid ----------
__global__ void __launch_bounds__(256, 5)
k_persist(const float* __restrict__ X,
          const int* __restrict__ rows,
          const int* __restrict__ cols,
          const float* __restrict__ vals,
          const float* __restrict__ W1,
          const float* __restrict__ W2,
          const float* __restrict__ Wd1,
          const float* __restrict__ bd1,
          const float* __restrict__ Wd2,
          const float* __restrict__ bd2,
          float* __restrict__ out,
          int N, int E) {
    __shared__ float sbuf[920];
    const int tid = threadIdx.x;
    const int bid = blockIdx.x;
    const unsigned base = *((volatile unsigned*)&g_calls);

    const int gN = (N + 255) / 256;        // node tiles
    const int nQ = N;                      // one quad per node
    const int quadsPerBlk = 256 / 4;       // 64
    const int quadStride = NBLK * quadsPerBlk;

    // ===================== P0: gemm1 (tiles) + hist/rank (edges) ============
    {
        float* sW = sbuf;                  // 896 floats
        for (int t = tid; t < DIM * Hdim; t += blockDim.x)
            sW[t] = W1[t];
        __syncthreads();

        for (int tile = bid; tile < gN; tile += NBLK) {
            int i = tile * 256 + tid;
            if (i < N) {
                const float4* x4 = (const float4*)(X + (long)i * DIM);
                float acc[Hdim];
#pragma unroll
                for (int j = 0; j < Hdim; ++j) acc[j] = 0.f;
#pragma unroll
                for (int k4 = 0; k4 < DIM / 4; ++k4) {
                    float4 x = x4[k4];
                    const float* w = &sW[k4 * 4 * Hdim];
#pragma unroll
                    for (int j = 0; j < Hdim; ++j)
                        acc[j] += x.x * w[j] + x.y * w[Hdim + j]
                                + x.z * w[2 * Hdim + j] + x.w * w[3 * Hdim + j];
                }
                g_Y1h[i * 4 + 0] = pack4h(acc[0], acc[1], acc[2], acc[3]);
                g_Y1h[i * 4 + 1] = pack4h(acc[4], acc[5], acc[6], acc[7]);
                g_Y1h[i * 4 + 2] = pack4h(acc[8], acc[9], acc[10], acc[11]);
                g_Y1h[i * 4 + 3] = pack4h(acc[12], acc[13], 0.f, 0.f);
            }
        }
        // histogram + rank, strided over edges
        for (int e = bid * 256 + tid; e < E; e += NBLK * 256) {
            int rk = atomicAdd(&g_cnt[rows[e]], 1);
            g_rank[e] = rk;
        }
    }
    gbar(1, base);

    // ===================== P1: scan (bucket bases) ==========================
    {
        int* wsum  = (int*)&sbuf[900];
        int* bbase = (int*)&sbuf[910];
        for (int tile = bid; tile < gN; tile += NBLK) {
            int i = tile * 256 + tid;
            int v = (i < N) ? __ldg(&g_cnt[i]) : 0;

            int lane = tid & 31, w = tid >> 5;
            int x = v;
#pragma unroll
            for (int off = 1; off < 32; off <<= 1) {
                int y = __shfl_up_sync(0xffffffffu, x, off);
                if (lane >= off) x += y;
            }
            if (lane == 31) wsum[w] = x;
            __syncthreads();
            if (tid < 8) {
                int s = wsum[tid];
#pragma unroll
                for (int off = 1; off < 8; off <<= 1) {
                    int y = __shfl_up_sync(0xffu, s, off);
                    if (tid >= off) s += y;
                }
                wsum[tid] = s;
                if (tid == 7) *bbase = atomicAdd(&g_cnt[NMAX], s);
            }
            __syncthreads();
            if (i < N) {
                int excl = (x - v) + ((w > 0) ? wsum[w - 1] : 0);
                g_start[i] = *bbase + excl;
            }
            __syncthreads();
        }
    }
    gbar(2, base);

    // ===================== P2: fill (atomic-free scatter) ===================
    for (int e = bid * 256 + tid; e < E; e += NBLK * 256) {
        int r = rows[e];
        int pos = __ldg(&g_start[r]) + __ldg(&g_rank[e]);
        g_edge[pos] = make_int2(cols[e], __float_as_int(vals[e]));
    }
    gbar(3, base);

    // ===================== P3: agg1  Y2h = pack(relu(agg(Y1h)) @ W2) ========
    {
        float* sW = sbuf;                  // W2 padded 14x16
        for (int t = tid; t < Hdim * 16; t += blockDim.x) {
            int k = t >> 4, j = t & 15;
            sW[t] = (j < Hdim) ? W2[k * Hdim + j] : 0.f;
        }
        __syncthreads();

        int q = tid & 3;
        for (int i = bid * quadsPerBlk + (tid >> 2); i < nQ; i += quadStride) {
            int s = __ldg(&g_start[i]);
            int c = __ldg(&g_cnt[i]);
            float4 acc = csr_agg4(g_Y1h, s, c, q);
            acc.x = fmaxf(acc.x, 0.f); acc.y = fmaxf(acc.y, 0.f);
            acc.z = fmaxf(acc.z, 0.f); acc.w = fmaxf(acc.w, 0.f);

            float h[16];
            group_bcast(acc, h, tid & 31);

            int j0 = q * 4;
            float y[4] = {0.f, 0.f, 0.f, 0.f};
#pragma unroll
            for (int k = 0; k < Hdim; ++k) {
                float hk = h[k];
#pragma unroll
                for (int d = 0; d < 4; ++d)
                    y[d] += hk * sW[k * 16 + j0 + d];
            }
            g_Y2h[(long)i * 4 + q] = pack4h(y[0], y[1], y[2], y[3]);
        }
    }
    gbar(4, base);

    // ===================== P4: agg2 -> heads -> out (+ restore) =============
    {
        float* sW1 = sbuf;                 // 224
        float* sW2 = sbuf + 224;           // 224
        float* sB1 = sbuf + 448;           // 16
        float* sB2 = sbuf + 464;           // 16
        for (int t = tid; t < Hdim * 16; t += blockDim.x) {
            int k = t >> 4, j = t & 15;
            sW1[t] = (j < Hdim) ? Wd1[k * Hdim + j] : 0.f;
            sW2[t] = Wd2[k * PD + j];
        }
        if (tid < 16) {
            sB1[tid] = (tid < Hdim) ? bd1[tid] : 0.f;
            sB2[tid] = bd2[tid];
        }
        __syncthreads();

        int q = tid & 3;
        for (int i = bid * quadsPerBlk + (tid >> 2); i < nQ; i += quadStride) {
            int s = __ldg(&g_start[i]);
            int c = __ldg(&g_cnt[i]);
            float4 acc = csr_agg4(g_Y2h, s, c, q);
            if (q == 0) g_cnt[i] = 0;      // self-restore histogram (read happened above)
            acc.x = fmaxf(acc.x, 0.f); acc.y = fmaxf(acc.y, 0.f);
            acc.z = fmaxf(acc.z, 0.f); acc.w = fmaxf(acc.w, 0.f);

            float h[16];
            group_bcast(acc, h, tid & 31);

            int j0 = q * 4;
            float pd[4], pp[4];
#pragma unroll
            for (int d = 0; d < 4; ++d) { pd[d] = sB1[j0 + d]; pp[d] = sB2[j0 + d]; }
#pragma unroll
            for (int k = 0; k < Hdim; ++k) {
                float hk = h[k];
#pragma unroll
                for (int d = 0; d < 4; ++d) {
                    pd[d] += hk * sW1[k * 16 + j0 + d];
                    pp[d] += hk * sW2[k * 16 + j0 + d];
                }
            }

            float* o = out + (long)i * OUTC;
#pragma unroll
            for (int d = 0; d < 4; ++d) {
                int j = j0 + d;
                if (j < Hdim) {
                    float t = ftanh(pd[d]);
                    o[j] = (j < LATC) ? t : fsoftplus(t + SP_INV_1);
                }
                o[Hdim + j] = ftanh(pp[d]);   // U(14) + m(2)
            }
        }
    }

    // finalize: last CTA restores scan total and bumps call counter
    __syncthreads();
    if (tid == 0) {
        __threadfence();
        unsigned f = atomicAdd(&g_fin, 1u) + 1u;
        if (f == (base + 1u) * NBLK) {
            g_cnt[NMAX] = 0;               // restore scan-total accumulator
            __threadfence();
            atomicAdd(&g_calls, 1u);
        }
    }
}

// ---------------- launch: ONE persistent kernel -----------------------------
extern "C" void kernel_launch(void* const* d_in, const int* in_sizes, int n_in,
                              void* d_out, int out_size) {
    const float* X    = (const float*)d_in[0];
    const int*   rows = (const int*)d_in[1];
    const int*   cols = (const int*)d_in[2];
    const float* vals = (const float*)d_in[3];
    const float* W1   = (const float*)d_in[4];
    const float* W2   = (const float*)d_in[5];
    const float* Wd1  = (const float*)d_in[6];
    const float* bd1  = (const float*)d_in[7];
    const float* Wd2  = (const float*)d_in[8];
    const float* bd2  = (const float*)d_in[9];
    float* out = (float*)d_out;

    int N = in_sizes[0] / DIM;
    int E = in_sizes[1];

    k_persist<<<NBLK, 256>>>(X, rows, cols, vals, W1, W2, Wd1, bd1, Wd2, bd2,
                             out, N, E);
}

// round 11
// speedup vs baseline: 1.4656x; 1.2548x over previous
#include <cuda_runtime.h>
#include <cuda_fp16.h>
#include <math.h>

// Problem constants (fixed by the dataset)
#define NMAX   100000
#define EMAX   1000000
#define DIM    64
#define Hdim   14     // H = 2*LAT
#define PD     16     // P = (LAT+1)*R
#define LATC   7
#define OUTC   30     // 7 loc + 7 scale + 14 U + 2 m
#define SP_INV_1 0.5413248546129181f

// ---------------- scratch (static device globals; zero-init at load) -------
// g_cnt is SELF-RESTORING: agg2 zeroes it after reading, so no memset node.
__device__ uint2  g_Y1h[NMAX * 4];    // X@W1 (fp16, padded 16 feats, pads=0)
__device__ uint2  g_Y2h[NMAX * 4];    // relu(agg1)@W2 (fp16)
__device__ int    g_cnt[NMAX + 1];    // degree histogram; [NMAX] = scan total
__device__ int    g_start[NMAX];      // bucket base offsets (disjoint)
__device__ int    g_rank[EMAX];       // within-row rank of each edge
__device__ int2   g_edge[EMAX];       // (col, val_bits) bucketed by row

// pack 4 fp32 -> uint2 of half2
__device__ __forceinline__ uint2 pack4h(float a, float b, float c, float d) {
    half2 lo = __floats2half2_rn(a, b);
    half2 hi = __floats2half2_rn(c, d);
    uint2 r;
    r.x = *reinterpret_cast<unsigned*>(&lo);
    r.y = *reinterpret_cast<unsigned*>(&hi);
    return r;
}
__device__ __forceinline__ void fma_h4(float4& acc, uint2 r, float v) {
    half2 lo = *reinterpret_cast<half2*>(&r.x);
    half2 hi = *reinterpret_cast<half2*>(&r.y);
    float2 f01 = __half22float2(lo);
    float2 f23 = __half22float2(hi);
    acc.x += v * f01.x; acc.y += v * f01.y;
    acc.z += v * f23.x; acc.w += v * f23.y;
}

// ---------------- K_FAT: gemm1 (blocks < gN) || histogram+rank (rest) ------
__global__ void k_fat(const float* __restrict__ X, const float* __restrict__ W1,
                      const int* __restrict__ rows, int N, int E, int gN) {
    if ((int)blockIdx.x >= gN) {
        int e = (blockIdx.x - gN) * blockDim.x + threadIdx.x;
        if (e < E) {
            int rk = atomicAdd(&g_cnt[rows[e]], 1);
            g_rank[e] = rk;
        }
        return;
    }

    __shared__ float sW[DIM * Hdim];   // 896 floats
    for (int t = threadIdx.x; t < DIM * Hdim; t += blockDim.x)
        sW[t] = W1[t];
    __syncthreads();

    int i = blockIdx.x * blockDim.x + threadIdx.x;
    if (i >= N) return;

    const float4* x4 = (const float4*)(X + (long)i * DIM);
    float acc[Hdim];
#pragma unroll
    for (int j = 0; j < Hdim; ++j) acc[j] = 0.f;

#pragma unroll
    for (int k4 = 0; k4 < DIM / 4; ++k4) {
        float4 x = x4[k4];
        const float* w = &sW[k4 * 4 * Hdim];
#pragma unroll
        for (int j = 0; j < Hdim; ++j)
            acc[j] += x.x * w[j] + x.y * w[Hdim + j]
                    + x.z * w[2 * Hdim + j] + x.w * w[3 * Hdim + j];
    }

    g_Y1h[i * 4 + 0] = pack4h(acc[0], acc[1], acc[2], acc[3]);
    g_Y1h[i * 4 + 1] = pack4h(acc[4], acc[5], acc[6], acc[7]);
    g_Y1h[i * 4 + 2] = pack4h(acc[8], acc[9], acc[10], acc[11]);
    g_Y1h[i * 4 + 3] = pack4h(acc[12], acc[13], 0.f, 0.f);
}

// ---------------- one-pass scan: disjoint bucket bases via atomic total -----
__global__ void k_scan(int N) {
    int t = threadIdx.x;
    int i = blockIdx.x * 256 + t;
    int v = (i < N) ? g_cnt[i] : 0;

    int lane = t & 31, w = t >> 5;
    int x = v;
#pragma unroll
    for (int off = 1; off < 32; off <<= 1) {
        int y = __shfl_up_sync(0xffffffffu, x, off);
        if (lane >= off) x += y;
    }

    __shared__ int wsum[8];
    __shared__ int bbase;
    if (lane == 31) wsum[w] = x;
    __syncthreads();
    if (t < 8) {
        int s = wsum[t];
#pragma unroll
        for (int off = 1; off < 8; off <<= 1) {
            int y = __shfl_up_sync(0xffu, s, off);
            if (t >= off) s += y;
        }
        wsum[t] = s;
        if (t == 7) bbase = atomicAdd(&g_cnt[NMAX], s);  // block base
    }
    __syncthreads();

    if (i < N) {
        int excl = (x - v) + ((w > 0) ? wsum[w - 1] : 0);
        g_start[i] = bbase + excl;
    }
}

// atomic-free scatter using precomputed ranks
__global__ void k_fill(const int* __restrict__ rows, const int* __restrict__ cols,
                       const float* __restrict__ vals, int E) {
    int e = blockIdx.x * blockDim.x + threadIdx.x;
    if (e >= E) return;
    int r = rows[e];
    int pos = g_start[r] + g_rank[e];
    g_edge[pos] = make_int2(cols[e], __float_as_int(vals[e]));
}

// ---------------- helpers ---------------------------------------------------
__device__ __forceinline__ float ftanh(float x) {
    x = fminf(fmaxf(x, -15.f), 15.f);
    float e = __expf(2.f * x);
    return (e - 1.f) / (e + 1.f);
}
__device__ __forceinline__ float fsoftplus(float x) {
    return log1pf(__expf(x));   // input range ~[-0.46, 1.54]: safe
}

// 4 lanes per node; lane owns fp16 chunk q (8B).
// Edge records are lane-distributed: lane q loads edge e+q, quad shares via
// width-4 shuffles (lanes of a quad are convergent: same trip count).
// Next record prefetched to overlap with gathers.
__device__ __forceinline__ float4 csr_agg4(const uint2* __restrict__ src,
                                           int s, int cnt, int q,
                                           unsigned qmask) {
    int e = s, end = s + cnt;
    float4 acc = make_float4(0.f, 0.f, 0.f, 0.f);

    if (e + 4 <= end) {
        int2 myed = __ldg(&g_edge[e + q]);
        for (;;) {
            int2 ed[4];
#pragma unroll
            for (int u = 0; u < 4; ++u) {
                ed[u].x = __shfl_sync(qmask, myed.x, u, 4);
                ed[u].y = __shfl_sync(qmask, myed.y, u, 4);
            }
            uint2 sv[4];
#pragma unroll
            for (int u = 0; u < 4; ++u)
                sv[u] = __ldg(&src[(long)ed[u].x * 4 + q]);

            bool more = (e + 8 <= end);
            int2 nxt;
            if (more) nxt = __ldg(&g_edge[e + 4 + q]);

#pragma unroll
            for (int u = 0; u < 4; ++u)
                fma_h4(acc, sv[u], __int_as_float(ed[u].y));

            e += 4;
            if (!more) break;
            myed = nxt;
        }
    }
    for (; e < end; ++e) {
        int2 ed = __ldg(&g_edge[e]);
        uint2 sv = __ldg(&src[(long)ed.x * 4 + q]);
        fma_h4(acc, sv, __int_as_float(ed.y));
    }
    return acc;
}

// broadcast the 16 h-values of this node's lane-quad into h[16]
__device__ __forceinline__ void group_bcast(float4 acc, float* h, int lane) {
    int base = lane & ~3;
#pragma unroll
    for (int sq = 0; sq < 4; ++sq) {
        h[4 * sq + 0] = __shfl_sync(0xffffffffu, acc.x, base + sq);
        h[4 * sq + 1] = __shfl_sync(0xffffffffu, acc.y, base + sq);
        h[4 * sq + 2] = __shfl_sync(0xffffffffu, acc.z, base + sq);
        h[4 * sq + 3] = __shfl_sync(0xffffffffu, acc.w, base + sq);
    }
}

// ---------------- K_AGG1: Y2h = pack(relu(agg(Y1h)) @ W2) ------------------
__global__ void k_agg1(const float* __restrict__ W2, int N) {
    __shared__ float sW[Hdim * 16];    // W2 padded to 14x16, pads = 0
    for (int t = threadIdx.x; t < Hdim * 16; t += blockDim.x) {
        int k = t >> 4, j = t & 15;
        sW[t] = (j < Hdim) ? W2[k * Hdim + j] : 0.f;
    }
    __syncthreads();

    int tid = blockIdx.x * blockDim.x + threadIdx.x;
    int i = tid >> 2, q = tid & 3;
    int lane = threadIdx.x & 31;
    unsigned qmask = 0xFu << (lane & 28);
    bool valid = (i < N);
    int ic = valid ? i : 0;

    int s = __ldg(&g_start[ic]);
    int c = valid ? __ldg(&g_cnt[ic]) : 0;
    float4 acc = csr_agg4(g_Y1h, s, c, q, qmask);

    acc.x = fmaxf(acc.x, 0.f); acc.y = fmaxf(acc.y, 0.f);
    acc.z = fmaxf(acc.z, 0.f); acc.w = fmaxf(acc.w, 0.f);

    float h[16];
    group_bcast(acc, h, lane);

    int j0 = q * 4;
    float y[4] = {0.f, 0.f, 0.f, 0.f};
#pragma unroll
    for (int k = 0; k < Hdim; ++k) {
        float hk = h[k];
#pragma unroll
        for (int d = 0; d < 4; ++d)
            y[d] += hk * sW[k * 16 + j0 + d];
    }

    if (valid)
        g_Y2h[(long)i * 4 + q] = pack4h(y[0], y[1], y[2], y[3]);
}

// ---------------- K_AGG2: agg(Y2h) -> relu -> heads -> out (+restore) ------
__global__ void k_agg2(const float* __restrict__ Wd1, const float* __restrict__ bd1,
                       const float* __restrict__ Wd2, const float* __restrict__ bd2,
                       float* __restrict__ out, int N) {
    __shared__ float sW1[Hdim * 16];   // Wd1 padded 14x16
    __shared__ float sW2[Hdim * 16];   // Wd2 14x16 (natural)
    __shared__ float sB1[16];
    __shared__ float sB2[16];
    for (int t = threadIdx.x; t < Hdim * 16; t += blockDim.x) {
        int k = t >> 4, j = t & 15;
        sW1[t] = (j < Hdim) ? Wd1[k * Hdim + j] : 0.f;
        sW2[t] = Wd2[k * PD + j];
    }
    if (threadIdx.x < 16) {
        sB1[threadIdx.x] = (threadIdx.x < Hdim) ? bd1[threadIdx.x] : 0.f;
        sB2[threadIdx.x] = bd2[threadIdx.x];
    }
    __syncthreads();

    int tid = blockIdx.x * blockDim.x + threadIdx.x;
    int i = tid >> 2, q = tid & 3;
    int lane = threadIdx.x & 31;
    unsigned qmask = 0xFu << (lane & 28);
    bool valid = (i < N);
    int ic = valid ? i : 0;

    int s = __ldg(&g_start[ic]);
    int c = valid ? __ldg(&g_cnt[ic]) : 0;
    float4 acc = csr_agg4(g_Y2h, s, c, q, qmask);

    // self-restore histogram for the next call (load of c precedes this store
    // in program order for all lanes of the warp)
    if (valid && q == 0) g_cnt[i] = 0;
    if (tid == 0) g_cnt[NMAX] = 0;     // restore scan-total accumulator

    acc.x = fmaxf(acc.x, 0.f); acc.y = fmaxf(acc.y, 0.f);
    acc.z = fmaxf(acc.z, 0.f); acc.w = fmaxf(acc.w, 0.f);

    float h[16];
    group_bcast(acc, h, lane);

    int j0 = q * 4;
    float pd[4], pp[4];
#pragma unroll
    for (int d = 0; d < 4; ++d) { pd[d] = sB1[j0 + d]; pp[d] = sB2[j0 + d]; }
#pragma unroll
    for (int k = 0; k < Hdim; ++k) {
        float hk = h[k];
#pragma unroll
        for (int d = 0; d < 4; ++d) {
            pd[d] += hk * sW1[k * 16 + j0 + d];
            pp[d] += hk * sW2[k * 16 + j0 + d];
        }
    }

    if (valid) {
        float* o = out + (long)i * OUTC;
#pragma unroll
        for (int d = 0; d < 4; ++d) {
            int j = j0 + d;
            if (j < Hdim) {
                float t = ftanh(pd[d]);
                o[j] = (j < LATC) ? t : fsoftplus(t + SP_INV_1);
            }
            o[Hdim + j] = ftanh(pp[d]);   // 16 perturb outputs: U(14) + m(2)
        }
    }
}

// ---------------- launch: 5 kernels, no memset ------------------------------
extern "C" void kernel_launch(void* const* d_in, const int* in_sizes, int n_in,
                              void* d_out, int out_size) {
    const float* X    = (const float*)d_in[0];
    const int*   rows = (const int*)d_in[1];
    const int*   cols = (const int*)d_in[2];
    const float* vals = (const float*)d_in[3];
    const float* W1   = (const float*)d_in[4];
    const float* W2   = (const float*)d_in[5];
    const float* Wd1  = (const float*)d_in[6];
    const float* bd1  = (const float*)d_in[7];
    const float* Wd2  = (const float*)d_in[8];
    const float* bd2  = (const float*)d_in[9];
    float* out = (float*)d_out;

    int N = in_sizes[0] / DIM;
    int E = in_sizes[1];

    const int T = 256;
    int gN  = (N + T - 1) / T;
    int gE  = (E + T - 1) / T;
    int g4N = (N * 4 + T - 1) / T;
    int nb  = (N + 255) / 256;

    k_fat <<<gN + gE, T>>>(X, W1, rows, N, E, gN);   // gemm1 || histogram+rank
    k_scan<<<nb, 256>>>(N);
    k_fill<<<gE, T>>>(rows, cols, vals, E);
    k_agg1<<<g4N, T>>>(W2, N);
    k_agg2<<<g4N, T>>>(Wd1, bd1, Wd2, bd2, out, N);
}